// round 10
// baseline (speedup 1.0000x reference)
#include <cuda_runtime.h>
#include <cstdint>

// Problem constants (fixed by the reference implementation)
#define NFEAT  23
#define EMB    10
#define TOTALD 65      // sum(FEATURE_DIMS)
#define DMAXD  4
#define CH     230     // NFEAT * EMB
#define PAIRS  115     // CH / 2 — each thread owns an (e, e+1) pair of one feature
#define TR     16      // rows per tile
#define NTILES 8
#define RPB    (TR * NTILES)              // 128 rows per block
#define IN_TILE_BYTES  (TR * TOTALD * 4)  // 4160 B  (mult of 16)
#define OUT_TILE_BYTES (TR * CH * 4)      // 14720 B (mult of 16)

__constant__ int c_dims[NFEAT] = {4,4,4,4,4,4,4,4,4,4,4,4,2,2,1,4,1,1,1,1,1,1,2};
__constant__ int c_offs[NFEAT] = {0,4,8,12,16,20,24,28,32,36,40,44,48,50,52,53,57,58,59,60,61,62,63};

// ---- async-proxy helpers: bulk G2S (mbarrier) and bulk S2G (bulk_group) ----
__device__ __forceinline__ uint32_t smem_u32(const void* p) {
    return (uint32_t)__cvta_generic_to_shared(p);
}
__device__ __forceinline__ void mbar_init(uint32_t mbar, uint32_t count) {
    asm volatile("mbarrier.init.shared.b64 [%0], %1;" :: "r"(mbar), "r"(count) : "memory");
}
__device__ __forceinline__ void mbar_expect_tx(uint32_t mbar, uint32_t bytes) {
    asm volatile("mbarrier.arrive.expect_tx.shared.b64 _, [%0], %1;"
                 :: "r"(mbar), "r"(bytes) : "memory");
}
__device__ __forceinline__ void bulk_g2s(uint32_t dst_s, const void* src,
                                         uint32_t bytes, uint32_t mbar) {
    asm volatile(
        "cp.async.bulk.shared::cta.global.mbarrier::complete_tx::bytes "
        "[%0], [%1], %2, [%3];"
        :: "r"(dst_s), "l"(src), "r"(bytes), "r"(mbar) : "memory");
}
__device__ __forceinline__ void bulk_s2g(void* gdst, uint32_t src_s, uint32_t bytes) {
    asm volatile(
        "cp.async.bulk.global.shared::cta.bulk_group [%0], [%1], %2;"
        :: "l"(gdst), "r"(src_s), "r"(bytes) : "memory");
}
#define BULK_COMMIT()      asm volatile("cp.async.bulk.commit_group;" ::: "memory")
#define BULK_WAIT_READ_1() asm volatile("cp.async.bulk.wait_group.read 1;" ::: "memory")
#define BULK_WAIT_0()      asm volatile("cp.async.bulk.wait_group 0;" ::: "memory")
__device__ __forceinline__ void mbar_wait(uint32_t mbar, uint32_t parity) {
    asm volatile(
        "{\n\t"
        ".reg .pred P;\n\t"
        "WAIT_%=:\n\t"
        "mbarrier.try_wait.parity.acquire.cta.shared::cta.b64 P, [%0], %1, 0x989680;\n\t"
        "@P bra.uni DONE_%=;\n\t"
        "bra.uni WAIT_%=;\n\t"
        "DONE_%=:\n\t"
        "}"
        :: "r"(mbar), "r"(parity) : "memory");
}

// blockDim=256: tid%128 = channel-pair p (0..114 active), tid/128 = row phase.
// Both streams are DMA-driven: inputs arrive via bulk G2S (mbarrier), results
// are written to an smem tile with cheap STS.64 (no global scoreboard, no
// L1tex store wavefronts) and drained by ONE bulk S2G per tile. Double
// buffering on both sides; wait_group.read gates output-buffer reuse.
__global__ __launch_bounds__(256, 6)
void Projection_5171140624940_kernel(const float* __restrict__ x,
                                     const float* __restrict__ W,
                                     const float* __restrict__ b,
                                     float* __restrict__ out,
                                     int rows)
{
    __shared__ __align__(16) float xs[2][TR * TOTALD];   // 2 x 4160 B
    __shared__ __align__(16) float os[2][TR * CH];       // 2 x 14720 B
    __shared__ __align__(8)  uint64_t mb[2];

    const int tid   = threadIdx.x;
    const int p     = tid & 127;
    const int rslot = tid >> 7;
    const bool active = (p < PAIRS);

    // Per-thread channel-pair metadata + register-resident weights.
    float w0[DMAXD], w1[DMAXD];
    float b0 = 0.f, b1 = 0.f;
    int off = 0, dim = 0;
    if (active) {
        const int f = p / 5;
        const int e = (p - f * 5) * 2;
        off = c_offs[f];
        dim = c_dims[f];
        #pragma unroll
        for (int j = 0; j < DMAXD; ++j) {
            w0[j] = __ldg(W + f * (DMAXD * EMB) + j * EMB + e);
            w1[j] = __ldg(W + f * (DMAXD * EMB) + j * EMB + e + 1);
        }
        b0 = __ldg(b + f * EMB + e);
        b1 = __ldg(b + f * EMB + e + 1);
    }

    const int rBase = blockIdx.x * RPB;

    if (rBase + RPB <= rows) {
        // ---- Fast path: 8 tiles of 16 rows, double-buffered in & out ----
        const uint32_t mbs[2]  = { smem_u32(&mb[0]), smem_u32(&mb[1]) };
        const uint32_t xss[2]  = { smem_u32(xs[0]),  smem_u32(xs[1])  };
        const uint32_t oss[2]  = { smem_u32(os[0]),  smem_u32(os[1])  };

        if (tid == 0) {
            mbar_init(mbs[0], 1);
            mbar_init(mbs[1], 1);
            asm volatile("fence.proxy.async.shared::cta;" ::: "memory");
        }
        __syncthreads();

        // Prefetch input tile 0.
        if (tid == 0) {
            mbar_expect_tx(mbs[0], IN_TILE_BYTES);
            bulk_g2s(xss[0], x + (size_t)rBase * TOTALD, IN_TILE_BYTES, mbs[0]);
        }

        #pragma unroll
        for (int t = 0; t < NTILES; ++t) {
            const int buf = t & 1;
            // Issue input t+1: its buffer's last readers finished before the
            // end-of-iteration barrier of t-1.
            if (tid == 0 && t + 1 < NTILES) {
                mbar_expect_tx(mbs[buf ^ 1], IN_TILE_BYTES);
                bulk_g2s(xss[buf ^ 1],
                         x + (size_t)(rBase + (t + 1) * TR) * TOTALD,
                         IN_TILE_BYTES, mbs[buf ^ 1]);
            }
            // Wait for input tile t (slot reused every 2 tiles -> parity).
            mbar_wait(mbs[buf], (t >> 1) & 1);
            // Gate os[buf] reuse: allow tile t-1's store in flight, require
            // tile t-2's store (same buffer) to have finished READING smem.
            if (tid == 0) { BULK_WAIT_READ_1(); }
            __syncthreads();

            if (active) {
                const float* xb = xs[buf];
                float* ob = os[buf];
                #pragma unroll
                for (int lr = rslot; lr < TR; lr += 2) {
                    const float* xr = xb + lr * TOTALD + off;
                    float s0 = b0, s1 = b1;
                    #pragma unroll
                    for (int j = 0; j < DMAXD; ++j) {
                        if (j < dim) {
                            const float xv = xr[j];
                            s0 = fmaf(xv, w0[j], s0);
                            s1 = fmaf(xv, w1[j], s1);
                        }
                    }
                    // STS.64, conflict-free (8B lane stride), no scoreboard
                    *reinterpret_cast<float2*>(ob + lr * CH + 2 * p) =
                        make_float2(s0, s1);
                }
            }
            __syncthreads();   // all STS visible; xs[buf] free for t+1's DMA

            if (tid == 0) {
                asm volatile("fence.proxy.async.shared::cta;" ::: "memory");
                bulk_s2g(out + (size_t)(rBase + t * TR) * CH, oss[buf],
                         OUT_TILE_BYTES);
                BULK_COMMIT();
            }
        }
        if (tid == 0) { BULK_WAIT_0(); }   // drain stores before exit
    } else {
        // ---- Tail path (unused for B=524288): synchronous everything ----
        for (int t0 = 0; t0 < RPB; t0 += TR) {
            const int tileStart = rBase + t0;
            if (tileStart >= rows) break;
            const int tileRows = min(TR, rows - tileStart);

            const float* src = x + (size_t)tileStart * TOTALD;
            for (int i = tid; i < tileRows * TOTALD; i += 256)
                xs[0][i] = __ldcs(src + i);
            __syncthreads();

            if (active) {
                for (int lr = rslot; lr < tileRows; lr += 2) {
                    const float* xr = xs[0] + lr * TOTALD + off;
                    float s0 = b0, s1 = b1;
                    #pragma unroll
                    for (int j = 0; j < DMAXD; ++j) {
                        if (j < dim) {
                            const float xv = xr[j];
                            s0 = fmaf(xv, w0[j], s0);
                            s1 = fmaf(xv, w1[j], s1);
                        }
                    }
                    __stcs(reinterpret_cast<float2*>(
                               out + (size_t)(tileStart + lr) * CH + 2 * p),
                           make_float2(s0, s1));
                }
            }
            __syncthreads();
        }
    }
}

extern "C" void kernel_launch(void* const* d_in, const int* in_sizes, int n_in,
                              void* d_out, int out_size)
{
    const float* x = (const float*)d_in[0];   // [B, 65] f32
    const float* W = (const float*)d_in[1];   // [23, 4, 10] f32 (masked)
    const float* b = (const float*)d_in[2];   // [23, 10] f32
    // d_in[3] = idx (int32) — compile-time constant metadata, ignored.
    float* out = (float*)d_out;               // [B, 23, 10] f32

    const int rows = in_sizes[0] / TOTALD;    // 524288
    const int grid = (rows + RPB - 1) / RPB;  // 4096

    Projection_5171140624940_kernel<<<grid, 256>>>(x, W, b, out, rows);
}